// round 2
// baseline (speedup 1.0000x reference)
#include <cuda_runtime.h>
#include <math.h>

#define NTOK 8192
#define DDIM 1024
#define NEXP 16
#define NTHR 512          // 16 warps
#define NBLK 128          // 128 blocks * 16 warps * 4 tokens = 8192
#define TPB  64           // tokens per block

// ---- scratch (device globals: no allocation allowed) ----
__device__ float g_S[DDIM];          // column sums of h^2 ; zero at load, re-zeroed by moe_loss
__device__ float g_G[NEXP * NEXP];   // Gram matrix

// ============================================================================
// K1: warp-autonomous fused router + combine.
//   One staging barrier, then each warp handles 4 tokens (2 passes of 2)
//   with no further __syncthreads. Tail: per-block h^2 column partials.
// ============================================================================
extern "C" __global__ void __launch_bounds__(NTHR, 1)
moe_main(const float* __restrict__ x,
         const float* __restrict__ gate_w,
         const float* __restrict__ gate_b,
         const float* __restrict__ sh_e,
         const float* __restrict__ rt_e,
         float* __restrict__ out)
{
    extern __shared__ float sm[];
    float* gate_s = sm;                       // NEXP*DDIM (64 KB)
    float* r_s    = gate_s + NEXP * DDIM;     // NEXP*DDIM (64 KB)
    float* sh_s   = r_s + NEXP * DDIM;        // DDIM (4 KB) : shared-expert sum
    float* gb_s   = sh_s + DDIM;              // NEXP

    const int tid  = threadIdx.x;
    const int warp = tid >> 5;
    const int lane = tid & 31;

    // ---- stage weights (one-time) ----
    for (int i = tid; i < NEXP * DDIM / 4; i += NTHR) {
        ((float4*)gate_s)[i] = ((const float4*)gate_w)[i];
        ((float4*)r_s)[i]    = ((const float4*)rt_e)[i];
    }
    for (int i = tid; i < DDIM / 4; i += NTHR) {
        float4 a = ((const float4*)sh_e)[i];
        float4 b = ((const float4*)(sh_e + DDIM))[i];
        float4 c; c.x = a.x + b.x; c.y = a.y + b.y; c.z = a.z + b.z; c.w = a.w + b.w;
        ((float4*)sh_s)[i] = c;
    }
    if (tid < NEXP) gb_s[tid] = gate_b[tid];
    __syncthreads();

    const int tok0 = (blockIdx.x * 16 + warp) * 4;   // this warp's 4 tokens

    #pragma unroll
    for (int half = 0; half < 2; half++) {
        const int tA = tok0 + 2 * half;

        // ---- load h for 2 tokens into registers (d = 128*i + 4*lane) ----
        float4 hA[8], hB[8];
        const float* xA = x + (size_t)tA * DDIM + 4 * lane;
        #pragma unroll
        for (int i = 0; i < 8; i++) hA[i] = *(const float4*)(xA + 128 * i);
        #pragma unroll
        for (int i = 0; i < 8; i++) hB[i] = *(const float4*)(xA + DDIM + 128 * i);

        // ---- logits: 2 chunks of 8 experts; butterfly reduce-scatter ----
        float stash[2];
        #pragma unroll
        for (int c = 0; c < 2; c++) {
            float acc[16];
            #pragma unroll
            for (int j = 0; j < 16; j++) acc[j] = 0.f;
            #pragma unroll
            for (int el = 0; el < 8; el++) {
                const float* gp = gate_s + (8 * c + el) * DDIM + 4 * lane;
                #pragma unroll
                for (int i = 0; i < 8; i++) {
                    float4 g = *(const float4*)(gp + 128 * i);
                    acc[el]     += g.x * hA[i].x + g.y * hA[i].y + g.z * hA[i].z + g.w * hA[i].w;
                    acc[8 + el] += g.x * hB[i].x + g.y * hB[i].y + g.z * hB[i].z + g.w * hB[i].w;
                }
            }
            // reduce-scatter 16 accs over 32 lanes: acc[j] (t=j>>3, e=8c+(j&7))
            float v8[8];
            #pragma unroll
            for (int j = 0; j < 8; j++) {
                float send = (lane & 16) ? acc[j] : acc[j + 8];
                float recv = __shfl_xor_sync(0xffffffffu, send, 16);
                v8[j] = ((lane & 16) ? acc[j + 8] : acc[j]) + recv;
            }
            float v4[4];
            #pragma unroll
            for (int j = 0; j < 4; j++) {
                float send = (lane & 8) ? v8[j] : v8[j + 4];
                float recv = __shfl_xor_sync(0xffffffffu, send, 8);
                v4[j] = ((lane & 8) ? v8[j + 4] : v8[j]) + recv;
            }
            float v2[2];
            #pragma unroll
            for (int j = 0; j < 2; j++) {
                float send = (lane & 4) ? v2[0] : 0.f; // placeholder (overwritten below)
                (void)send;
                float s2 = (lane & 4) ? v4[j] : v4[j + 2];
                float r2 = __shfl_xor_sync(0xffffffffu, s2, 4);
                v2[j] = ((lane & 4) ? v4[j + 2] : v4[j]) + r2;
            }
            float s1 = (lane & 2) ? v2[0] : v2[1];
            float r1 = __shfl_xor_sync(0xffffffffu, s1, 2);
            float z  = ((lane & 2) ? v2[1] : v2[0]) + r1;
            z += __shfl_xor_sync(0xffffffffu, z, 1);
            stash[c] = z;   // lane l holds j=(l>>1)&15 : t=j>>3, e=8c+(j&7)
        }

        // ---- gather into router layout: lane L -> (tt=L>>4, e=L&15) ----
        const int e  = lane & 15;
        const int tt = lane >> 4;
        const int src = (((tt << 3) | (e & 7)) << 1);
        float l0 = __shfl_sync(0xffffffffu, stash[0], src);
        float l1 = __shfl_sync(0xffffffffu, stash[1], src);
        float lg = ((e & 8) ? l1 : l0) + gb_s[e];

        // ---- top-2 per 16-lane half (lowest-index tie-break) ----
        float v1 = lg; int j1 = e;
        #pragma unroll
        for (int off = 8; off; off >>= 1) {
            float ov = __shfl_xor_sync(0xffffffffu, v1, off);
            int   oj = __shfl_xor_sync(0xffffffffu, j1, off);
            if (ov > v1 || (ov == v1 && oj < j1)) { v1 = ov; j1 = oj; }
        }
        float lgm = (e == j1) ? -1e30f : lg;
        float v2r = lgm; int j2 = e;
        #pragma unroll
        for (int off = 8; off; off >>= 1) {
            float ov = __shfl_xor_sync(0xffffffffu, v2r, off);
            int   oj = __shfl_xor_sync(0xffffffffu, j2, off);
            if (ov > v2r || (ov == v2r && oj < j2)) { v2r = ov; j2 = oj; }
        }
        float w0t = 1.f / (1.f + __expf(v2r - v1));   // softmax denom cancels

        const float w0A = __shfl_sync(0xffffffffu, w0t, 0);
        const float w0B = __shfl_sync(0xffffffffu, w0t, 16);
        const int i0A = __shfl_sync(0xffffffffu, j1, 0);
        const int i0B = __shfl_sync(0xffffffffu, j1, 16);
        const int i1A = __shfl_sync(0xffffffffu, j2, 0);
        const int i1B = __shfl_sync(0xffffffffu, j2, 16);
        const float w1A = 1.f - w0A, w1B = 1.f - w0B;

        // ---- combine + store ----
        {
            float* op = out + (size_t)tA * DDIM + 4 * lane;
            const float* r0p = r_s + i0A * DDIM + 4 * lane;
            const float* r1p = r_s + i1A * DDIM + 4 * lane;
            const float* svp = sh_s + 4 * lane;
            #pragma unroll
            for (int i = 0; i < 8; i++) {
                float4 r0 = *(const float4*)(r0p + 128 * i);
                float4 r1 = *(const float4*)(r1p + 128 * i);
                float4 sv = *(const float4*)(svp + 128 * i);
                float4 o;
                o.x = hA[i].x * (sv.x + w0A * r0.x + w1A * r1.x);
                o.y = hA[i].y * (sv.y + w0A * r0.y + w1A * r1.y);
                o.z = hA[i].z * (sv.z + w0A * r0.z + w1A * r1.z);
                o.w = hA[i].w * (sv.w + w0A * r0.w + w1A * r1.w);
                *(float4*)(op + 128 * i) = o;
            }
        }
        {
            float* op = out + (size_t)(tA + 1) * DDIM + 4 * lane;
            const float* r0p = r_s + i0B * DDIM + 4 * lane;
            const float* r1p = r_s + i1B * DDIM + 4 * lane;
            const float* svp = sh_s + 4 * lane;
            #pragma unroll
            for (int i = 0; i < 8; i++) {
                float4 r0 = *(const float4*)(r0p + 128 * i);
                float4 r1 = *(const float4*)(r1p + 128 * i);
                float4 sv = *(const float4*)(svp + 128 * i);
                float4 o;
                o.x = hB[i].x * (sv.x + w0B * r0.x + w1B * r1.x);
                o.y = hB[i].y * (sv.y + w0B * r0.y + w1B * r1.y);
                o.z = hB[i].z * (sv.z + w0B * r0.z + w1B * r1.z);
                o.w = hB[i].w * (sv.w + w0B * r0.w + w1B * r1.w);
                *(float4*)(op + 128 * i) = o;
            }
        }
    }

    // ---- tail: h^2 column partials for this block's 64 tokens ----
    // warp w covers dims [64w, 64w+64); lane: 2 dims. x rows are L2-hot.
    {
        const int dbase = 64 * warp + 2 * lane;
        float s0 = 0.f, s1 = 0.f;
        const float* xp = x + (size_t)blockIdx.x * TPB * DDIM + dbase;
        #pragma unroll 4
        for (int n = 0; n < TPB; n++) {
            float2 v = *(const float2*)(xp + (size_t)n * DDIM);
            s0 += v.x * v.x; s1 += v.y * v.y;
        }
        atomicAdd(&g_S[dbase],     s0);
        atomicAdd(&g_S[dbase + 1], s1);
    }
}

// ============================================================================
// K2: Gram rows  G[e,f] = sum_d r_e[d] * r_f[d] * S[d]
// ============================================================================
extern "C" __global__ void __launch_bounds__(256, 1)
moe_gram(const float* __restrict__ rt_e)
{
    extern __shared__ float sm2[];
    float* rs  = sm2;                   // NEXP*DDIM (64 KB)
    float* Ss  = rs + NEXP * DDIM;      // DDIM
    float* red = Ss + DDIM;             // 8*NEXP

    const int tid = threadIdx.x;
    for (int i = tid; i < NEXP * DDIM / 4; i += 256)
        ((float4*)rs)[i] = ((const float4*)rt_e)[i];
    for (int i = tid; i < DDIM; i += 256) Ss[i] = g_S[i];
    __syncthreads();

    const int e = blockIdx.x;
    float acc[NEXP];
    #pragma unroll
    for (int f = 0; f < NEXP; f++) acc[f] = 0.f;

    for (int d = tid; d < DDIM; d += 256) {
        float v = rs[e * DDIM + d] * Ss[d];
        #pragma unroll
        for (int f = 0; f < NEXP; f++) acc[f] += v * rs[f * DDIM + d];
    }

    const int wid = tid >> 5, lane = tid & 31;
    #pragma unroll
    for (int f = 0; f < NEXP; f++) {
        #pragma unroll
        for (int off = 16; off; off >>= 1)
            acc[f] += __shfl_xor_sync(0xffffffffu, acc[f], off);
    }
    if (lane == 0) {
        #pragma unroll
        for (int f = 0; f < NEXP; f++) red[wid * NEXP + f] = acc[f];
    }
    __syncthreads();
    if (tid < NEXP) {
        float s = 0.f;
        #pragma unroll
        for (int w = 0; w < 8; w++) s += red[w * NEXP + tid];
        g_G[e * NEXP + tid] = s;
    }
}

// ============================================================================
// K3: final diversity loss; re-zero g_S for next graph replay
// ============================================================================
extern "C" __global__ void moe_loss(float* __restrict__ out, int has_loss, int loss_idx)
{
    const int lane = threadIdx.x;   // 32 threads
    const int e = lane & 15;
    float n = sqrtf(g_G[e * NEXP + e]);
    n = fmaxf(n, 1e-8f);
    float s = 0.f;
    #pragma unroll
    for (int f = 0; f < NEXP; f++) {
        float nf = __shfl_sync(0xffffffffu, n, f);
        if (f != e) {
            float sim = g_G[e * NEXP + f] / (n * nf);
            sim = fminf(1.f, fmaxf(-1.f, sim));
            s += sim;
        }
    }
    if (lane >= 16) s = 0.f;
    #pragma unroll
    for (int off = 16; off; off >>= 1) s += __shfl_xor_sync(0xffffffffu, s, off);
    if (lane == 0 && has_loss)
        out[loss_idx] = s / (float)(NEXP * (NEXP - 1)) * 0.1f;

    for (int i = lane; i < DDIM; i += 32) g_S[i] = 0.f;
}

// ============================================================================
extern "C" void kernel_launch(void* const* d_in, const int* in_sizes, int n_in,
                              void* d_out, int out_size)
{
    const float* x  = (const float*)d_in[0];
    const float* gw = (const float*)d_in[1];
    const float* gb = (const float*)d_in[2];
    const float* se = (const float*)d_in[3];
    const float* re = (const float*)d_in[4];
    float* out = (float*)d_out;

    const int SMEM1 = (2 * NEXP * DDIM + DDIM + NEXP) * 4;
    const int SMEM2 = (NEXP * DDIM + DDIM + 8 * NEXP) * 4;

    cudaFuncSetAttribute((const void*)moe_main, cudaFuncAttributeMaxDynamicSharedMemorySize, SMEM1);
    cudaFuncSetAttribute((const void*)moe_gram, cudaFuncAttributeMaxDynamicSharedMemorySize, SMEM2);

    moe_main<<<NBLK, NTHR, SMEM1>>>(x, gw, gb, se, re, out);
    moe_gram<<<NEXP, 256, SMEM2>>>(re);

    int has_loss = (out_size > NTOK * DDIM) ? 1 : 0;
    moe_loss<<<1, 32>>>(out, has_loss, out_size - 1);
}

// round 3
// speedup vs baseline: 2.0408x; 2.0408x over previous
#include <cuda_runtime.h>
#include <math.h>

#define NTOK 8192
#define DDIM 1024
#define NEXP 16
#define GRP  8            // tokens per group
#define TPB  16           // tokens per block
#define NBLK 512          // 512 * 16 = 8192
#define FULL 0xffffffffu

// ---- scratch (device globals: no allocation allowed) ----
__device__ float g_S[DDIM];          // column sums of h^2 ; zero at load, re-zeroed by moe_loss
__device__ float g_G[NEXP * NEXP];   // Gram matrix

// ============================================================================
// K1: fused router + combine. 256 threads (8 warps), 2 blocks/SM.
//   warp = expert-pair for logits; gate rows in registers; h staged in smem.
//   Router recomputed per-warp in regs (no extra sync); dim-sliced combine
//   with sh-vector and h^2 accumulators in registers.
// ============================================================================
extern "C" __global__ void __launch_bounds__(256, 2)
moe_main(const float* __restrict__ x,
         const float* __restrict__ gate_w,
         const float* __restrict__ gate_b,
         const float* __restrict__ sh_e,
         const float* __restrict__ rt_e,
         float* __restrict__ out)
{
    __shared__ float h_s[GRP * DDIM];      // 32 KB
    __shared__ float logit_s[GRP * 17];    // padded stride 17

    const int tid  = threadIdx.x;
    const int warp = tid >> 5;
    const int lane = tid & 31;

    // ---- gate rows 2*warp, 2*warp+1 in registers (float4, d = 4*lane + 128*i) ----
    float4 ga4[8], gb4[8];
    {
        const float4* gwp = (const float4*)(gate_w + 2 * warp * DDIM);
        #pragma unroll
        for (int i = 0; i < 8; i++) {
            ga4[i] = gwp[32 * i + lane];
            gb4[i] = gwp[256 + 32 * i + lane];
        }
    }

    // ---- this thread's combine dim-slice + shared-expert sum in regs ----
    const int d0 = 128 * warp + 4 * lane;
    float4 sh4;
    {
        float4 a = *(const float4*)(sh_e + d0);
        float4 b = *(const float4*)(sh_e + DDIM + d0);
        sh4.x = a.x + b.x; sh4.y = a.y + b.y; sh4.z = a.z + b.z; sh4.w = a.w + b.w;
    }
    float s4x = 0.f, s4y = 0.f, s4z = 0.f, s4w = 0.f;   // h^2 partials

    #pragma unroll
    for (int grp = 0; grp < TPB / GRP; grp++) {
        const int tbase = blockIdx.x * TPB + grp * GRP;

        // ---- stage 8 token rows (coalesced float4) ----
        {
            const float4* xs = (const float4*)(x + (size_t)tbase * DDIM);
            float4* hd = (float4*)h_s;
            #pragma unroll
            for (int i = 0; i < 8; i++) hd[i * 256 + tid] = xs[i * 256 + tid];
        }
        __syncthreads();

        // ---- logits: this warp's 2 experts x 8 tokens ----
        float acc[16];
        #pragma unroll
        for (int j = 0; j < 16; j++) acc[j] = 0.f;
        #pragma unroll
        for (int t = 0; t < 8; t++) {
            float aA = 0.f, aB = 0.f;
            #pragma unroll
            for (int i = 0; i < 8; i++) {
                float4 h4 = *(const float4*)&h_s[t * DDIM + 4 * lane + 128 * i];
                float4 g0 = ga4[i], g1 = gb4[i];
                aA += g0.x * h4.x + g0.y * h4.y + g0.z * h4.z + g0.w * h4.w;
                aB += g1.x * h4.x + g1.y * h4.y + g1.z * h4.z + g1.w * h4.w;
            }
            acc[2 * t]     = aA;
            acc[2 * t + 1] = aB;
        }

        // ---- reduce-scatter 16 accs across 32 lanes (verified in R2) ----
        // final: lane l holds full sum of acc[(l>>1)&15]
        float v8[8];
        #pragma unroll
        for (int j = 0; j < 8; j++) {
            float send = (lane & 16) ? acc[j] : acc[j + 8];
            float recv = __shfl_xor_sync(FULL, send, 16);
            v8[j] = ((lane & 16) ? acc[j + 8] : acc[j]) + recv;
        }
        float v4[4];
        #pragma unroll
        for (int j = 0; j < 4; j++) {
            float send = (lane & 8) ? v8[j] : v8[j + 4];
            float recv = __shfl_xor_sync(FULL, send, 8);
            v4[j] = ((lane & 8) ? v8[j + 4] : v8[j]) + recv;
        }
        float v2[2];
        #pragma unroll
        for (int j = 0; j < 2; j++) {
            float s2 = (lane & 4) ? v4[j] : v4[j + 2];
            float r2 = __shfl_xor_sync(FULL, s2, 4);
            v2[j] = ((lane & 4) ? v4[j + 2] : v4[j]) + r2;
        }
        float s1 = (lane & 2) ? v2[0] : v2[1];
        float r1 = __shfl_xor_sync(FULL, s1, 2);
        float z  = ((lane & 2) ? v2[1] : v2[0]) + r1;
        z += __shfl_xor_sync(FULL, z, 1);

        if (!(lane & 1)) {
            const int j = (lane >> 1) & 15;              // j = 2*t + e'
            logit_s[(j >> 1) * 17 + 2 * warp + (j & 1)] = z;
        }
        __syncthreads();

        // ---- router: every warp routes all 8 tokens (redundant, no sync) ----
        float w0r[4]; int i0r[4], i1r[4];
        #pragma unroll
        for (int p = 0; p < 4; p++) {
            const int t = 2 * p + (lane >> 4);
            const int e = lane & 15;
            float lg = logit_s[t * 17 + e] + __ldg(&gate_b[e]);
            float v1 = lg; int j1 = e;
            #pragma unroll
            for (int off = 8; off; off >>= 1) {
                float ov = __shfl_xor_sync(FULL, v1, off);
                int   oj = __shfl_xor_sync(FULL, j1, off);
                if (ov > v1 || (ov == v1 && oj < j1)) { v1 = ov; j1 = oj; }
            }
            float lgm = (e == j1) ? -1e30f : lg;
            float vv2 = lgm; int j2 = e;
            #pragma unroll
            for (int off = 8; off; off >>= 1) {
                float ov = __shfl_xor_sync(FULL, vv2, off);
                int   oj = __shfl_xor_sync(FULL, j2, off);
                if (ov > vv2 || (ov == vv2 && oj < j2)) { vv2 = ov; j2 = oj; }
            }
            w0r[p] = 1.f / (1.f + __expf(vv2 - v1));     // softmax denom cancels
            i0r[p] = j1; i1r[p] = j2;
        }

        // ---- combine (dim-sliced): warp covers dims [128w, 128w+128) ----
        #pragma unroll
        for (int t = 0; t < 8; t++) {
            const int src = (t & 1) << 4;
            const float w0 = __shfl_sync(FULL, w0r[t >> 1], src);
            const int   i0 = __shfl_sync(FULL, i0r[t >> 1], src);
            const int   i1 = __shfl_sync(FULL, i1r[t >> 1], src);
            const float w1 = 1.f - w0;
            float4 h4 = *(const float4*)&h_s[t * DDIM + d0];
            float4 r0 = *(const float4*)(rt_e + i0 * DDIM + d0);
            float4 r1 = *(const float4*)(rt_e + i1 * DDIM + d0);
            float4 o;
            o.x = h4.x * (sh4.x + w0 * r0.x + w1 * r1.x);
            o.y = h4.y * (sh4.y + w0 * r0.y + w1 * r1.y);
            o.z = h4.z * (sh4.z + w0 * r0.z + w1 * r1.z);
            o.w = h4.w * (sh4.w + w0 * r0.w + w1 * r1.w);
            *(float4*)(out + (size_t)(tbase + t) * DDIM + d0) = o;
            s4x += h4.x * h4.x; s4y += h4.y * h4.y;
            s4z += h4.z * h4.z; s4w += h4.w * h4.w;
        }
        __syncthreads();   // protect h_s before next stage
    }

    atomicAdd(&g_S[d0 + 0], s4x);
    atomicAdd(&g_S[d0 + 1], s4y);
    atomicAdd(&g_S[d0 + 2], s4z);
    atomicAdd(&g_S[d0 + 3], s4w);
}

// ============================================================================
// K2: Gram rows  G[e,f] = sum_d r_e[d] * r_f[d] * S[d]   (no staging, L2-hot)
// ============================================================================
extern "C" __global__ void __launch_bounds__(256, 1)
moe_gram(const float* __restrict__ rt_e)
{
    __shared__ float red[8 * NEXP];
    const int tid = threadIdx.x;
    const int e = blockIdx.x;

    float acc[NEXP];
    #pragma unroll
    for (int f = 0; f < NEXP; f++) acc[f] = 0.f;

    for (int d = tid; d < DDIM; d += 256) {
        float v = __ldg(&rt_e[e * DDIM + d]) * g_S[d];
        #pragma unroll
        for (int f = 0; f < NEXP; f++) acc[f] += v * __ldg(&rt_e[f * DDIM + d]);
    }

    const int wid = tid >> 5, lane = tid & 31;
    #pragma unroll
    for (int f = 0; f < NEXP; f++) {
        #pragma unroll
        for (int off = 16; off; off >>= 1)
            acc[f] += __shfl_xor_sync(FULL, acc[f], off);
    }
    if (lane == 0) {
        #pragma unroll
        for (int f = 0; f < NEXP; f++) red[wid * NEXP + f] = acc[f];
    }
    __syncthreads();
    if (tid < NEXP) {
        float s = 0.f;
        #pragma unroll
        for (int w = 0; w < 8; w++) s += red[w * NEXP + tid];
        g_G[e * NEXP + tid] = s;
    }
}

// ============================================================================
// K3: final diversity loss; re-zero g_S for next graph replay
// ============================================================================
extern "C" __global__ void moe_loss(float* __restrict__ out, int has_loss, int loss_idx)
{
    const int lane = threadIdx.x;   // 32 threads
    const int e = lane & 15;
    float n = sqrtf(g_G[e * NEXP + e]);
    n = fmaxf(n, 1e-8f);
    float s = 0.f;
    #pragma unroll
    for (int f = 0; f < NEXP; f++) {
        float nf = __shfl_sync(FULL, n, f);
        if (f != e) {
            float sim = g_G[e * NEXP + f] / (n * nf);
            sim = fminf(1.f, fmaxf(-1.f, sim));
            s += sim;
        }
    }
    if (lane >= 16) s = 0.f;
    #pragma unroll
    for (int off = 16; off; off >>= 1) s += __shfl_xor_sync(FULL, s, off);
    if (lane == 0 && has_loss)
        out[loss_idx] = s / (float)(NEXP * (NEXP - 1)) * 0.1f;

    for (int i = lane; i < DDIM; i += 32) g_S[i] = 0.f;
}

// ============================================================================
extern "C" void kernel_launch(void* const* d_in, const int* in_sizes, int n_in,
                              void* d_out, int out_size)
{
    const float* x  = (const float*)d_in[0];
    const float* gw = (const float*)d_in[1];
    const float* gb = (const float*)d_in[2];
    const float* se = (const float*)d_in[3];
    const float* re = (const float*)d_in[4];
    float* out = (float*)d_out;

    moe_main<<<NBLK, 256>>>(x, gw, gb, se, re, out);
    moe_gram<<<NEXP, 256>>>(re);

    int has_loss = (out_size > NTOK * DDIM) ? 1 : 0;
    moe_loss<<<1, 32>>>(out, has_loss, out_size - 1);
}

// round 4
// speedup vs baseline: 2.3419x; 1.1476x over previous
#include <cuda_runtime.h>
#include <math.h>

#define NTOK 8192
#define DDIM 1024
#define NEXP 16
#define GRP  8            // tokens per group
#define NGRPS 4           // groups per block
#define TPB  (GRP * NGRPS)   // 32 tokens per block
#define NBLK (NTOK / TPB)    // 256 -> single wave (2 blocks/SM resident)
#define FULL 0xffffffffu

// ---- scratch (device globals: no allocation allowed) ----
__device__ float g_S[DDIM];          // column sums of h^2 ; zero at load, re-zeroed by moe_loss
__device__ float g_G[NEXP * NEXP];   // Gram matrix

__device__ __forceinline__ void cpasync16(float* dst, const float* src) {
    unsigned d = (unsigned)__cvta_generic_to_shared(dst);
    asm volatile("cp.async.cg.shared.global [%0], [%1], 16;" :: "r"(d), "l"(src));
}
__device__ __forceinline__ void cp_commit() { asm volatile("cp.async.commit_group;"); }
__device__ __forceinline__ void cp_wait1()  { asm volatile("cp.async.wait_group 1;"); }

// ============================================================================
// K1: fused router + combine, cp.async double-buffered h staging.
//   256 threads (8 warps), 2 blocks/SM. Warp = expert-pair for logits (gate
//   rows in regs); redundant per-warp router; dim-sliced combine.
// ============================================================================
extern "C" __global__ void __launch_bounds__(256, 2)
moe_main(const float* __restrict__ x,
         const float* __restrict__ gate_w,
         const float* __restrict__ gate_b,
         const float* __restrict__ sh_e,
         const float* __restrict__ rt_e,
         float* __restrict__ out)
{
    __shared__ float h_s[2][GRP * DDIM];   // 2 x 32 KB
    __shared__ float logit_s[GRP * 17];    // padded stride 17

    const int tid  = threadIdx.x;
    const int warp = tid >> 5;
    const int lane = tid & 31;
    const int tok0 = blockIdx.x * TPB;

    // ---- prefetch groups 0 and 1 ----
    #pragma unroll
    for (int i = 0; i < 8; i++)
        cpasync16(&h_s[0][4 * (i * 256 + tid)],
                  x + (size_t)tok0 * DDIM + 4 * (i * 256 + tid));
    cp_commit();
    #pragma unroll
    for (int i = 0; i < 8; i++)
        cpasync16(&h_s[1][4 * (i * 256 + tid)],
                  x + (size_t)(tok0 + GRP) * DDIM + 4 * (i * 256 + tid));
    cp_commit();

    // ---- gate rows 2*warp, 2*warp+1 in registers (float4, d = 4*lane + 128*i) ----
    float4 ga4[8], gb4[8];
    {
        const float4* gwp = (const float4*)(gate_w + 2 * warp * DDIM);
        #pragma unroll
        for (int i = 0; i < 8; i++) {
            ga4[i] = gwp[32 * i + lane];
            gb4[i] = gwp[256 + 32 * i + lane];
        }
    }

    // ---- combine dim-slice + shared-expert sum in regs ----
    const int d0 = 128 * warp + 4 * lane;
    float4 sh4;
    {
        float4 a = *(const float4*)(sh_e + d0);
        float4 b = *(const float4*)(sh_e + DDIM + d0);
        sh4.x = a.x + b.x; sh4.y = a.y + b.y; sh4.z = a.z + b.z; sh4.w = a.w + b.w;
    }
    const float bias = __ldg(&gate_b[lane & 15]);
    float s4x = 0.f, s4y = 0.f, s4z = 0.f, s4w = 0.f;   // h^2 partials

    #pragma unroll
    for (int grp = 0; grp < NGRPS; grp++) {
        const int tbase = tok0 + grp * GRP;
        const float* hbuf = h_s[grp & 1];

        cp_wait1();          // group `grp` landed
        __syncthreads();     // visible to all warps

        // ---- logits: this warp's 2 experts x 8 tokens ----
        float acc[16];
        #pragma unroll
        for (int t = 0; t < 8; t++) {
            float aA = 0.f, aB = 0.f;
            #pragma unroll
            for (int i = 0; i < 8; i++) {
                float4 h4 = *(const float4*)&hbuf[t * DDIM + 4 * lane + 128 * i];
                float4 g0 = ga4[i], g1 = gb4[i];
                aA += g0.x * h4.x + g0.y * h4.y + g0.z * h4.z + g0.w * h4.w;
                aB += g1.x * h4.x + g1.y * h4.y + g1.z * h4.z + g1.w * h4.w;
            }
            acc[2 * t]     = aA;
            acc[2 * t + 1] = aB;
        }

        // ---- reduce-scatter 16 accs across 32 lanes ----
        // final: lane l holds full sum of acc[(l>>1)&15]
        float v8[8];
        #pragma unroll
        for (int j = 0; j < 8; j++) {
            float send = (lane & 16) ? acc[j] : acc[j + 8];
            float recv = __shfl_xor_sync(FULL, send, 16);
            v8[j] = ((lane & 16) ? acc[j + 8] : acc[j]) + recv;
        }
        float v4[4];
        #pragma unroll
        for (int j = 0; j < 4; j++) {
            float send = (lane & 8) ? v8[j] : v8[j + 4];
            float recv = __shfl_xor_sync(FULL, send, 8);
            v4[j] = ((lane & 8) ? v8[j + 4] : v8[j]) + recv;
        }
        float v2[2];
        #pragma unroll
        for (int j = 0; j < 2; j++) {
            float s2 = (lane & 4) ? v4[j] : v4[j + 2];
            float r2 = __shfl_xor_sync(FULL, s2, 4);
            v2[j] = ((lane & 4) ? v4[j + 2] : v4[j]) + r2;
        }
        float s1 = (lane & 2) ? v2[0] : v2[1];
        float r1 = __shfl_xor_sync(FULL, s1, 2);
        float z  = ((lane & 2) ? v2[1] : v2[0]) + r1;
        z += __shfl_xor_sync(FULL, z, 1);

        if (!(lane & 1)) {
            const int j = (lane >> 1) & 15;              // j = 2*t + e'
            logit_s[(j >> 1) * 17 + 2 * warp + (j & 1)] = z;
        }
        __syncthreads();

        // ---- router: every warp routes all 8 tokens (redundant, no sync) ----
        float w0r[4]; int i0r[4], i1r[4];
        const int e = lane & 15;
        #pragma unroll
        for (int p = 0; p < 4; p++) {
            const int t = 2 * p + (lane >> 4);
            float lg = logit_s[t * 17 + e] + bias;
            float v1 = lg; int j1 = e;
            #pragma unroll
            for (int off = 8; off; off >>= 1) {
                float ov = __shfl_xor_sync(FULL, v1, off);
                int   oj = __shfl_xor_sync(FULL, j1, off);
                if (ov > v1 || (ov == v1 && oj < j1)) { v1 = ov; j1 = oj; }
            }
            float lgm = (e == j1) ? -1e30f : lg;
            float vv2 = lgm; int j2 = e;
            #pragma unroll
            for (int off = 8; off; off >>= 1) {
                float ov = __shfl_xor_sync(FULL, vv2, off);
                int   oj = __shfl_xor_sync(FULL, j2, off);
                if (ov > vv2 || (ov == vv2 && oj < j2)) { vv2 = ov; j2 = oj; }
            }
            w0r[p] = 1.f / (1.f + __expf(vv2 - v1));     // softmax denom cancels
            i0r[p] = j1; i1r[p] = j2;
        }

        // ---- combine (dim-sliced): warp covers dims [128w, 128w+128) ----
        #pragma unroll
        for (int t = 0; t < 8; t++) {
            const int src = (t & 1) << 4;
            const float w0 = __shfl_sync(FULL, w0r[t >> 1], src);
            const int   i0 = __shfl_sync(FULL, i0r[t >> 1], src);
            const int   i1 = __shfl_sync(FULL, i1r[t >> 1], src);
            const float w1 = 1.f - w0;
            float4 h4 = *(const float4*)&hbuf[t * DDIM + d0];
            float4 r0 = *(const float4*)(rt_e + i0 * DDIM + d0);
            float4 r1 = *(const float4*)(rt_e + i1 * DDIM + d0);
            float4 o;
            o.x = h4.x * (sh4.x + w0 * r0.x + w1 * r1.x);
            o.y = h4.y * (sh4.y + w0 * r0.y + w1 * r1.y);
            o.z = h4.z * (sh4.z + w0 * r0.z + w1 * r1.z);
            o.w = h4.w * (sh4.w + w0 * r0.w + w1 * r1.w);
            *(float4*)(out + (size_t)(tbase + t) * DDIM + d0) = o;
            s4x += h4.x * h4.x; s4y += h4.y * h4.y;
            s4z += h4.z * h4.z; s4w += h4.w * h4.w;
        }
        __syncthreads();   // all warps done with this buffer

        // ---- prefetch group grp+2 into the buffer just freed ----
        if (grp + 2 < NGRPS) {
            const float* src = x + (size_t)(tok0 + (grp + 2) * GRP) * DDIM;
            float* dst = h_s[grp & 1];
            #pragma unroll
            for (int i = 0; i < 8; i++)
                cpasync16(&dst[4 * (i * 256 + tid)], src + 4 * (i * 256 + tid));
        }
        cp_commit();       // keep group counting consistent (empty groups OK)
    }

    atomicAdd(&g_S[d0 + 0], s4x);
    atomicAdd(&g_S[d0 + 1], s4y);
    atomicAdd(&g_S[d0 + 2], s4z);
    atomicAdd(&g_S[d0 + 3], s4w);
}

// ============================================================================
// K2: Gram rows  G[e,f] = sum_d r_e[d] * r_f[d] * S[d]   (L2-hot)
// ============================================================================
extern "C" __global__ void __launch_bounds__(256, 1)
moe_gram(const float* __restrict__ rt_e)
{
    __shared__ float red[8 * NEXP];
    const int tid = threadIdx.x;
    const int e = blockIdx.x;

    float acc[NEXP];
    #pragma unroll
    for (int f = 0; f < NEXP; f++) acc[f] = 0.f;

    for (int d = tid; d < DDIM; d += 256) {
        float v = __ldg(&rt_e[e * DDIM + d]) * g_S[d];
        #pragma unroll
        for (int f = 0; f < NEXP; f++) acc[f] += v * __ldg(&rt_e[f * DDIM + d]);
    }

    const int wid = tid >> 5, lane = tid & 31;
    #pragma unroll
    for (int f = 0; f < NEXP; f++) {
        #pragma unroll
        for (int off = 16; off; off >>= 1)
            acc[f] += __shfl_xor_sync(FULL, acc[f], off);
    }
    if (lane == 0) {
        #pragma unroll
        for (int f = 0; f < NEXP; f++) red[wid * NEXP + f] = acc[f];
    }
    __syncthreads();
    if (tid < NEXP) {
        float s = 0.f;
        #pragma unroll
        for (int w = 0; w < 8; w++) s += red[w * NEXP + tid];
        g_G[e * NEXP + tid] = s;
    }
}

// ============================================================================
// K3: final diversity loss; re-zero g_S for next graph replay
// ============================================================================
extern "C" __global__ void moe_loss(float* __restrict__ out, int has_loss, int loss_idx)
{
    const int lane = threadIdx.x;   // 32 threads
    const int e = lane & 15;
    float n = sqrtf(g_G[e * NEXP + e]);
    n = fmaxf(n, 1e-8f);
    float s = 0.f;
    #pragma unroll
    for (int f = 0; f < NEXP; f++) {
        float nf = __shfl_sync(FULL, n, f);
        if (f != e) {
            float sim = g_G[e * NEXP + f] / (n * nf);
            sim = fminf(1.f, fmaxf(-1.f, sim));
            s += sim;
        }
    }
    if (lane >= 16) s = 0.f;
    #pragma unroll
    for (int off = 16; off; off >>= 1) s += __shfl_xor_sync(FULL, s, off);
    if (lane == 0 && has_loss)
        out[loss_idx] = s / (float)(NEXP * (NEXP - 1)) * 0.1f;

    for (int i = lane; i < DDIM; i += 32) g_S[i] = 0.f;
}

// ============================================================================
extern "C" void kernel_launch(void* const* d_in, const int* in_sizes, int n_in,
                              void* d_out, int out_size)
{
    const float* x  = (const float*)d_in[0];
    const float* gw = (const float*)d_in[1];
    const float* gb = (const float*)d_in[2];
    const float* se = (const float*)d_in[3];
    const float* re = (const float*)d_in[4];
    float* out = (float*)d_out;

    moe_main<<<NBLK, 256>>>(x, gw, gb, se, re, out);
    moe_gram<<<NEXP, 256>>>(re);

    int has_loss = (out_size > NTOK * DDIM) ? 1 : 0;
    moe_loss<<<1, 32>>>(out, has_loss, out_size - 1);
}

// round 5
// speedup vs baseline: 2.4220x; 1.0342x over previous
#include <cuda_runtime.h>
#include <math.h>

#define NTOK 8192
#define DDIM 1024
#define NEXP 16
#define GRP  8               // tokens per group
#define NGRPS 4              // groups per block
#define TPB  (GRP * NGRPS)   // 32 tokens per block
#define NBLK (NTOK / TPB)    // 256 -> ~single wave (2 blocks/SM)
#define FULL 0xffffffffu
#define HBUF (GRP * DDIM)    // floats per h buffer

// ---- scratch (device globals: no allocation allowed) ----
__device__ float g_S[DDIM];          // column sums of h^2 ; zero at load, re-zeroed by moe_loss
__device__ float g_G[NEXP * NEXP];   // Gram matrix

__device__ __forceinline__ void cpasync16(float* dst, const float* src) {
    unsigned d = (unsigned)__cvta_generic_to_shared(dst);
    asm volatile("cp.async.cg.shared.global [%0], [%1], 16;" :: "r"(d), "l"(src));
}
__device__ __forceinline__ void cp_commit() { asm volatile("cp.async.commit_group;"); }
__device__ __forceinline__ void cp_wait1()  { asm volatile("cp.async.wait_group 1;"); }

// ============================================================================
// K1: fused router + combine. Triple-buffered cp.async h staging (96 KB dyn),
//   2 blocks/SM. Warp = expert-pair for logits (gate rows in regs);
//   serial-scan router (no shfl reductions); dim-sliced combine.
//   2 barriers per group.
// ============================================================================
extern "C" __global__ void __launch_bounds__(256, 2)
moe_main(const float* __restrict__ x,
         const float* __restrict__ gate_w,
         const float* __restrict__ gate_b,
         const float* __restrict__ sh_e,
         const float* __restrict__ rt_e,
         float* __restrict__ out)
{
    extern __shared__ float h_s[];         // 3 * 32 KB
    __shared__ float logit_s[GRP * 17];    // padded stride 17 (bias folded in)

    const int tid  = threadIdx.x;
    const int warp = tid >> 5;
    const int lane = tid & 31;
    const int tok0 = blockIdx.x * TPB;

    // ---- prefetch groups 0 and 1 ----
    #pragma unroll
    for (int i = 0; i < 8; i++)
        cpasync16(&h_s[0 * HBUF + 4 * (i * 256 + tid)],
                  x + (size_t)tok0 * DDIM + 4 * (i * 256 + tid));
    cp_commit();
    #pragma unroll
    for (int i = 0; i < 8; i++)
        cpasync16(&h_s[1 * HBUF + 4 * (i * 256 + tid)],
                  x + (size_t)(tok0 + GRP) * DDIM + 4 * (i * 256 + tid));
    cp_commit();

    // ---- gate rows 2*warp, 2*warp+1 in registers (float4, d = 4*lane + 128*i) ----
    float4 ga4[8], gb4[8];
    {
        const float4* gwp = (const float4*)(gate_w + 2 * warp * DDIM);
        #pragma unroll
        for (int i = 0; i < 8; i++) {
            ga4[i] = gwp[32 * i + lane];
            gb4[i] = gwp[256 + 32 * i + lane];
        }
    }
    const float biasA = __ldg(&gate_b[2 * warp]);
    const float biasB = __ldg(&gate_b[2 * warp + 1]);

    // ---- combine dim-slice + shared-expert sum in regs ----
    const int d0 = 128 * warp + 4 * lane;
    float4 sh4;
    {
        float4 a = *(const float4*)(sh_e + d0);
        float4 b = *(const float4*)(sh_e + DDIM + d0);
        sh4.x = a.x + b.x; sh4.y = a.y + b.y; sh4.z = a.z + b.z; sh4.w = a.w + b.w;
    }
    float s4x = 0.f, s4y = 0.f, s4z = 0.f, s4w = 0.f;   // h^2 partials

    #pragma unroll
    for (int grp = 0; grp < NGRPS; grp++) {
        const int tbase = tok0 + grp * GRP;
        const float* hbuf = h_s + (grp % 3) * HBUF;

        cp_wait1();          // group `grp` landed
        __syncthreads();     // visible to all; all warps past group grp-1 combine

        // ---- early prefetch grp+2 into buffer (grp+2)%3 (read last at grp-1) ----
        if (grp + 2 < NGRPS) {
            const float* src = x + (size_t)(tok0 + (grp + 2) * GRP) * DDIM;
            float* dst = h_s + ((grp + 2) % 3) * HBUF;
            #pragma unroll
            for (int i = 0; i < 8; i++)
                cpasync16(&dst[4 * (i * 256 + tid)], src + 4 * (i * 256 + tid));
        }
        cp_commit();         // commit every group to keep wait-counts aligned

        // ---- logits: this warp's 2 experts x 8 tokens ----
        float acc[16];
        #pragma unroll
        for (int t = 0; t < 8; t++) {
            float aA = 0.f, aB = 0.f;
            #pragma unroll
            for (int i = 0; i < 8; i++) {
                float4 h4 = *(const float4*)&hbuf[t * DDIM + 4 * lane + 128 * i];
                float4 g0 = ga4[i], g1 = gb4[i];
                aA += g0.x * h4.x + g0.y * h4.y + g0.z * h4.z + g0.w * h4.w;
                aB += g1.x * h4.x + g1.y * h4.y + g1.z * h4.z + g1.w * h4.w;
            }
            acc[2 * t]     = aA;
            acc[2 * t + 1] = aB;
        }

        // ---- reduce-scatter 16 accs across 32 lanes ----
        // final: lane l holds full sum of acc[(l>>1)&15]
        float v8[8];
        #pragma unroll
        for (int j = 0; j < 8; j++) {
            float send = (lane & 16) ? acc[j] : acc[j + 8];
            float recv = __shfl_xor_sync(FULL, send, 16);
            v8[j] = ((lane & 16) ? acc[j + 8] : acc[j]) + recv;
        }
        float v4[4];
        #pragma unroll
        for (int j = 0; j < 4; j++) {
            float send = (lane & 8) ? v8[j] : v8[j + 4];
            float recv = __shfl_xor_sync(FULL, send, 8);
            v4[j] = ((lane & 8) ? v8[j + 4] : v8[j]) + recv;
        }
        float v2[2];
        #pragma unroll
        for (int j = 0; j < 2; j++) {
            float s2 = (lane & 4) ? v2 /*dummy*/[0] * 0.f + ((lane & 4) ? v4[j] : v4[j + 2]) : v4[j + 2];
            // (simplified below — keep exact R4 pattern)
            s2 = (lane & 4) ? v4[j] : v4[j + 2];
            float r2 = __shfl_xor_sync(FULL, s2, 4);
            v2[j] = ((lane & 4) ? v4[j + 2] : v4[j]) + r2;
        }
        float s1 = (lane & 2) ? v2[0] : v2[1];
        float r1 = __shfl_xor_sync(FULL, s1, 2);
        float z  = ((lane & 2) ? v2[1] : v2[0]) + r1;
        z += __shfl_xor_sync(FULL, z, 1);

        if (!(lane & 1)) {
            const int j = (lane >> 1) & 15;              // j = 2*t + esub
            const int esub = j & 1;
            logit_s[(j >> 1) * 17 + 2 * warp + esub] = z + (esub ? biasB : biasA);
        }
        __syncthreads();

        // ---- router: serial top-2 scan; lane routes token (lane & 7) ----
        const int t_r = lane & 7;
        float v1 = -1e30f, vv2 = -1e30f; int j1 = 0, j2 = 0;
        #pragma unroll
        for (int e = 0; e < NEXP; e++) {
            float lg = logit_s[t_r * 17 + e];
            if (lg > v1)       { vv2 = v1; j2 = j1; v1 = lg; j1 = e; }
            else if (lg > vv2) { vv2 = lg; j2 = e; }
        }
        const float w0s = 1.f / (1.f + __expf(vv2 - v1));   // softmax denom cancels
        const int i0s = j1, i1s = j2;

        // ---- combine (dim-sliced): warp covers dims [128w, 128w+128) ----
        #pragma unroll
        for (int t = 0; t < 8; t++) {
            const float w0 = __shfl_sync(FULL, w0s, t);
            const int   i0 = __shfl_sync(FULL, i0s, t);
            const int   i1 = __shfl_sync(FULL, i1s, t);
            const float w1 = 1.f - w0;
            float4 h4 = *(const float4*)&hbuf[t * DDIM + d0];
            float4 r0 = *(const float4*)(rt_e + i0 * DDIM + d0);
            float4 r1 = *(const float4*)(rt_e + i1 * DDIM + d0);
            float4 o;
            o.x = h4.x * (sh4.x + w0 * r0.x + w1 * r1.x);
            o.y = h4.y * (sh4.y + w0 * r0.y + w1 * r1.y);
            o.z = h4.z * (sh4.z + w0 * r0.z + w1 * r1.z);
            o.w = h4.w * (sh4.w + w0 * r0.w + w1 * r1.w);
            *(float4*)(out + (size_t)(tbase + t) * DDIM + d0) = o;
            s4x += h4.x * h4.x; s4y += h4.y * h4.y;
            s4z += h4.z * h4.z; s4w += h4.w * h4.w;
        }
        // no end-of-group barrier: next group's first barrier protects buffers
    }

    atomicAdd(&g_S[d0 + 0], s4x);
    atomicAdd(&g_S[d0 + 1], s4y);
    atomicAdd(&g_S[d0 + 2], s4z);
    atomicAdd(&g_S[d0 + 3], s4w);
}

// ============================================================================
// K2: Gram rows  G[e,f] = sum_d r_e[d] * r_f[d] * S[d]   (L2-hot)
// ============================================================================
extern "C" __global__ void __launch_bounds__(256, 1)
moe_gram(const float* __restrict__ rt_e)
{
    __shared__ float red[8 * NEXP];
    const int tid = threadIdx.x;
    const int e = blockIdx.x;

    float acc[NEXP];
    #pragma unroll
    for (int f = 0; f < NEXP; f++) acc[f] = 0.f;

    for (int d = tid; d < DDIM; d += 256) {
        float v = __ldg(&rt_e[e * DDIM + d]) * g_S[d];
        #pragma unroll
        for (int f = 0; f < NEXP; f++) acc[f] += v * __ldg(&rt_e[f * DDIM + d]);
    }

    const int wid = tid >> 5, lane = tid & 31;
    #pragma unroll
    for (int f = 0; f < NEXP; f++) {
        #pragma unroll
        for (int off = 16; off; off >>= 1)
            acc[f] += __shfl_xor_sync(FULL, acc[f], off);
    }
    if (lane == 0) {
        #pragma unroll
        for (int f = 0; f < NEXP; f++) red[wid * NEXP + f] = acc[f];
    }
    __syncthreads();
    if (tid < NEXP) {
        float s = 0.f;
        #pragma unroll
        for (int w = 0; w < 8; w++) s += red[w * NEXP + tid];
        g_G[e * NEXP + tid] = s;
    }
}

// ============================================================================
// K3: final diversity loss; re-zero g_S for next graph replay
// ============================================================================
extern "C" __global__ void moe_loss(float* __restrict__ out, int has_loss, int loss_idx)
{
    const int lane = threadIdx.x;   // 32 threads
    const int e = lane & 15;
    float n = sqrtf(g_G[e * NEXP + e]);
    n = fmaxf(n, 1e-8f);
    float s = 0.f;
    #pragma unroll
    for (int f = 0; f < NEXP; f++) {
        float nf = __shfl_sync(FULL, n, f);
        if (f != e) {
            float sim = g_G[e * NEXP + f] / (n * nf);
            sim = fminf(1.f, fmaxf(-1.f, sim));
            s += sim;
        }
    }
    if (lane >= 16) s = 0.f;
    #pragma unroll
    for (int off = 16; off; off >>= 1) s += __shfl_xor_sync(FULL, s, off);
    if (lane == 0 && has_loss)
        out[loss_idx] = s / (float)(NEXP * (NEXP - 1)) * 0.1f;

    for (int i = lane; i < DDIM; i += 32) g_S[i] = 0.f;
}

// ============================================================================
extern "C" void kernel_launch(void* const* d_in, const int* in_sizes, int n_in,
                              void* d_out, int out_size)
{
    const float* x  = (const float*)d_in[0];
    const float* gw = (const float*)d_in[1];
    const float* gb = (const float*)d_in[2];
    const float* se = (const float*)d_in[3];
    const float* re = (const float*)d_in[4];
    float* out = (float*)d_out;

    const int SMEM1 = 3 * HBUF * (int)sizeof(float);   // 96 KB dynamic
    cudaFuncSetAttribute((const void*)moe_main,
                         cudaFuncAttributeMaxDynamicSharedMemorySize, SMEM1);

    moe_main<<<NBLK, 256, SMEM1>>>(x, gw, gb, se, re, out);
    moe_gram<<<NEXP, 256>>>(re);

    int has_loss = (out_size > NTOK * DDIM) ? 1 : 0;
    moe_loss<<<1, 32>>>(out, has_loss, out_size - 1);
}